// round 1
// baseline (speedup 1.0000x reference)
#include <cuda_runtime.h>
#include <math.h>

// Problem constants
#define BB   32
#define SS   1024
#define HH   2
#define EE   4
#define FF   16
#define VV   8
#define NT   (BB * SS)      // 32768 tokens
#define BHN  (BB * HH)      // 64 (b,h) pairs

// Scratch (no runtime allocation allowed)
__device__ float4 g_x[NT];                 // residual stream [token][E]
__device__ float2 g_q[BHN * SS];           // per-(b,h) q, pre-scaled by 1/sqrt(D)
__device__ float2 g_k[BHN * SS];
__device__ float2 g_v[BHN * SS];
__device__ float2 g_o[BHN * SS];           // attention output per (b,h,s)

// ---------------------------------------------------------------------------
// helpers
// ---------------------------------------------------------------------------
__device__ __forceinline__ void layernorm4(float4 x, const float* __restrict__ g,
                                           const float* __restrict__ b, float* h) {
    float mu = 0.25f * (x.x + x.y + x.z + x.w);
    float d0 = x.x - mu, d1 = x.y - mu, d2 = x.z - mu, d3 = x.w - mu;
    float var = 0.25f * (d0 * d0 + d1 * d1 + d2 * d2 + d3 * d3);
    float r = rsqrtf(var + 1e-5f);
    h[0] = d0 * r * __ldg(g + 0) + __ldg(b + 0);
    h[1] = d1 * r * __ldg(g + 1) + __ldg(b + 1);
    h[2] = d2 * r * __ldg(g + 2) + __ldg(b + 2);
    h[3] = d3 * r * __ldg(g + 3) + __ldg(b + 3);
}

// qkv projection for one token, write q/k/v in (b,h,s,d) float2 layout
__device__ __forceinline__ void qkv_project(int t, const float* h,
                                            const float* __restrict__ wqkv_l) {
    float acc[12];
#pragma unroll
    for (int f = 0; f < 12; f++) {
        const float* w = wqkv_l + f * EE;
        acc[f] = h[0] * __ldg(w) + h[1] * __ldg(w + 1) +
                 h[2] * __ldg(w + 2) + h[3] * __ldg(w + 3);
    }
    int b = t >> 10;            // t / S
    int s = t & (SS - 1);
    const float qs = 0.70710678118654752f;  // 1/sqrt(D), D=2
    g_q[(b * HH + 0) * SS + s] = make_float2(acc[0] * qs, acc[1] * qs);
    g_q[(b * HH + 1) * SS + s] = make_float2(acc[2] * qs, acc[3] * qs);
    g_k[(b * HH + 0) * SS + s] = make_float2(acc[4], acc[5]);
    g_k[(b * HH + 1) * SS + s] = make_float2(acc[6], acc[7]);
    g_v[(b * HH + 0) * SS + s] = make_float2(acc[8], acc[9]);
    g_v[(b * HH + 1) * SS + s] = make_float2(acc[10], acc[11]);
}

__device__ __forceinline__ float gelu_exact(float x) {
    return 0.5f * x * (1.0f + erff(x * 0.70710678118654752f));
}

// ---------------------------------------------------------------------------
// Kernel 1: embedding + LN1 + QKV (layer 0)
// ---------------------------------------------------------------------------
__global__ void embed_qkv_kernel(const int* __restrict__ token_ids,
                                 const float* __restrict__ emb,
                                 const float* __restrict__ ln1_g,
                                 const float* __restrict__ ln1_b,
                                 const float* __restrict__ wqkv) {
    int t = blockIdx.x * blockDim.x + threadIdx.x;
    if (t >= NT) return;
    int tok = __ldg(token_ids + t);
    const float* e = emb + tok * EE;
    float4 x = make_float4(__ldg(e), __ldg(e + 1), __ldg(e + 2), __ldg(e + 3));
    g_x[t] = x;
    float h[EE];
    layernorm4(x, ln1_g, ln1_b, h);
    qkv_project(t, h, wqkv);
}

// ---------------------------------------------------------------------------
// Kernel 2: attention for one layer.
// grid = BHN * 2 blocks (128), 256 threads, 2 queries/thread (512 q / block).
// ---------------------------------------------------------------------------
__global__ void __launch_bounds__(256) attn_kernel() {
    __shared__ float2 sK[SS];
    __shared__ float2 sV[SS];
    int bh    = blockIdx.x >> 1;
    int qbase = (blockIdx.x & 1) * 512;

    const float2* __restrict__ Kg = g_k + bh * SS;
    const float2* __restrict__ Vg = g_v + bh * SS;
    for (int i = threadIdx.x; i < SS; i += 256) {
        sK[i] = Kg[i];
        sV[i] = Vg[i];
    }
    __syncthreads();

    int qi0 = qbase + threadIdx.x;
    int qi1 = qi0 + 256;
    float2 qa = g_q[bh * SS + qi0];
    float2 qb = g_q[bh * SS + qi1];

    // pass 1: row max
    float ma = -1e30f, mb = -1e30f;
#pragma unroll 8
    for (int j = 0; j < SS; j++) {
        float2 kk = sK[j];
        float sa = fmaf(qa.x, kk.x, qa.y * kk.y);
        float sb = fmaf(qb.x, kk.x, qb.y * kk.y);
        ma = fmaxf(ma, sa);
        mb = fmaxf(mb, sb);
    }

    // pass 2: exp + weighted V accumulation
    float suma = 0.f, ax = 0.f, ay = 0.f;
    float sumb = 0.f, bx = 0.f, by = 0.f;
#pragma unroll 4
    for (int j = 0; j < SS; j++) {
        float2 kk = sK[j];
        float2 vv = sV[j];
        float sa = fmaf(qa.x, kk.x, qa.y * kk.y);
        float sb = fmaf(qb.x, kk.x, qb.y * kk.y);
        float pa = __expf(sa - ma);
        float pb = __expf(sb - mb);
        suma += pa;
        sumb += pb;
        ax = fmaf(pa, vv.x, ax);
        ay = fmaf(pa, vv.y, ay);
        bx = fmaf(pb, vv.x, bx);
        by = fmaf(pb, vv.y, by);
    }
    float ra = __frcp_rn(suma);
    float rb = __frcp_rn(sumb);
    g_o[bh * SS + qi0] = make_float2(ax * ra, ay * ra);
    g_o[bh * SS + qi1] = make_float2(bx * rb, by * rb);
}

// ---------------------------------------------------------------------------
// Kernel 3: x += wo*o ; FFN ; then either LN1+QKV of next layer or final logits
// ---------------------------------------------------------------------------
__global__ void post_attn_kernel(const float* __restrict__ wo_l,
                                 const float* __restrict__ ln2_g_l,
                                 const float* __restrict__ ln2_b_l,
                                 const float* __restrict__ w1_l,
                                 const float* __restrict__ b1_l,
                                 const float* __restrict__ w2_l,
                                 const float* __restrict__ b2_l,
                                 const float* __restrict__ ln1_g_next,  // null if last
                                 const float* __restrict__ ln1_b_next,
                                 const float* __restrict__ wqkv_next,
                                 const float* __restrict__ out_w,       // used if last
                                 float* __restrict__ out,
                                 int last) {
    int t = blockIdx.x * blockDim.x + threadIdx.x;
    if (t >= NT) return;
    int b = t >> 10;
    int s = t & (SS - 1);

    float4 x = g_x[t];
    float2 o0 = g_o[(b * HH + 0) * SS + s];
    float2 o1 = g_o[(b * HH + 1) * SS + s];
    float o[EE] = {o0.x, o0.y, o1.x, o1.y};

    // x += wo @ o
    float xv[EE] = {x.x, x.y, x.z, x.w};
#pragma unroll
    for (int f = 0; f < EE; f++) {
        const float* w = wo_l + f * EE;
        xv[f] += o[0] * __ldg(w) + o[1] * __ldg(w + 1) +
                 o[2] * __ldg(w + 2) + o[3] * __ldg(w + 3);
    }
    float4 xr = make_float4(xv[0], xv[1], xv[2], xv[3]);

    // FFN: x += w2 @ gelu(w1 @ LN2(x) + b1) + b2
    float h[EE];
    layernorm4(xr, ln2_g_l, ln2_b_l, h);
    float f1[FF];
#pragma unroll
    for (int f = 0; f < FF; f++) {
        const float* w = w1_l + f * EE;
        float acc = __ldg(b1_l + f) + h[0] * __ldg(w) + h[1] * __ldg(w + 1) +
                    h[2] * __ldg(w + 2) + h[3] * __ldg(w + 3);
        f1[f] = gelu_exact(acc);
    }
#pragma unroll
    for (int e = 0; e < EE; e++) {
        const float* w = w2_l + e * FF;
        float acc = __ldg(b2_l + e);
#pragma unroll
        for (int f = 0; f < FF; f++) acc = fmaf(f1[f], __ldg(w + f), acc);
        xv[e] += acc;
    }
    xr = make_float4(xv[0], xv[1], xv[2], xv[3]);
    g_x[t] = xr;

    if (last) {
        // logits = x @ out_w^T   [V=8]
#pragma unroll
        for (int v = 0; v < VV; v++) {
            const float* w = out_w + v * EE;
            out[t * VV + v] = xv[0] * __ldg(w) + xv[1] * __ldg(w + 1) +
                              xv[2] * __ldg(w + 2) + xv[3] * __ldg(w + 3);
        }
    } else {
        float hn[EE];
        layernorm4(xr, ln1_g_next, ln1_b_next, hn);
        qkv_project(t, hn, wqkv_next);
    }
}

// ---------------------------------------------------------------------------
// launch
// ---------------------------------------------------------------------------
extern "C" void kernel_launch(void* const* d_in, const int* in_sizes, int n_in,
                              void* d_out, int out_size) {
    const int*   token_ids = (const int*)d_in[0];
    const float* emb   = (const float*)d_in[1];
    const float* ln1_g = (const float*)d_in[2];
    const float* ln1_b = (const float*)d_in[3];
    const float* wqkv  = (const float*)d_in[4];
    const float* wo    = (const float*)d_in[5];
    const float* ln2_g = (const float*)d_in[6];
    const float* ln2_b = (const float*)d_in[7];
    const float* w1    = (const float*)d_in[8];
    const float* b1    = (const float*)d_in[9];
    const float* w2    = (const float*)d_in[10];
    const float* b2    = (const float*)d_in[11];
    const float* out_w = (const float*)d_in[12];
    float* out = (float*)d_out;

    const int TPB = 256;
    const int TOK_BLOCKS = NT / TPB;      // 128
    const int ATTN_BLOCKS = BHN * 2;      // 128

    // Layer 0
    embed_qkv_kernel<<<TOK_BLOCKS, TPB>>>(token_ids, emb, ln1_g, ln1_b, wqkv);
    attn_kernel<<<ATTN_BLOCKS, TPB>>>();
    post_attn_kernel<<<TOK_BLOCKS, TPB>>>(
        wo + 0 * EE * EE, ln2_g + 0 * EE, ln2_b + 0 * EE,
        w1 + 0 * FF * EE, b1 + 0 * FF, w2 + 0 * EE * FF, b2 + 0 * EE,
        ln1_g + 1 * EE, ln1_b + 1 * EE, wqkv + 1 * 3 * EE * EE,
        out_w, out, /*last=*/0);

    // Layer 1
    attn_kernel<<<ATTN_BLOCKS, TPB>>>();
    post_attn_kernel<<<TOK_BLOCKS, TPB>>>(
        wo + 1 * EE * EE, ln2_g + 1 * EE, ln2_b + 1 * EE,
        w1 + 1 * FF * EE, b1 + 1 * FF, w2 + 1 * EE * FF, b2 + 1 * EE,
        nullptr, nullptr, nullptr,
        out_w, out, /*last=*/1);
}

// round 2
// speedup vs baseline: 1.4016x; 1.4016x over previous
#include <cuda_runtime.h>
#include <math.h>

// Problem constants
#define BB   32
#define SS   1024
#define HH   2
#define EE   4
#define FF   16
#define VV   8
#define NT   (BB * SS)      // 32768 tokens
#define BHN  (BB * HH)      // 64 (b,h) pairs

typedef unsigned long long u64;

// Scratch (no runtime allocation allowed)
__device__ float4 g_x[NT];                 // residual stream [token][E]
__device__ float2 g_q[BHN * SS];           // per-(b,h) q, pre-scaled by 1/sqrt(D)
__device__ float2 g_k[BHN * SS];
__device__ float2 g_v[BHN * SS];
__device__ float2 g_o[BHN * SS];           // attention output per (b,h,s)

// ---------------------------------------------------------------------------
// f32x2 packed-math helpers (sm_103a)
// ---------------------------------------------------------------------------
__device__ __forceinline__ u64 pack2(float lo, float hi) {
    u64 r;
    asm("mov.b64 %0, {%1, %2};" : "=l"(r)
        : "r"(__float_as_uint(lo)), "r"(__float_as_uint(hi)));
    return r;
}
__device__ __forceinline__ void unpack2(u64 v, float& lo, float& hi) {
    unsigned a, b;
    asm("mov.b64 {%0, %1}, %2;" : "=r"(a), "=r"(b) : "l"(v));
    lo = __uint_as_float(a);
    hi = __uint_as_float(b);
}
#define FMA2(d, a, b, c) \
    asm("fma.rn.f32x2 %0, %1, %2, %3;" : "=l"(d) : "l"(a), "l"(b), "l"(c))

__device__ __forceinline__ float ex2f(float x) {
    float r;
    asm("ex2.approx.f32 %0, %1;" : "=f"(r) : "f"(x));
    return r;
}

// ---------------------------------------------------------------------------
// scalar helpers
// ---------------------------------------------------------------------------
__device__ __forceinline__ void layernorm4(float4 x, const float* __restrict__ g,
                                           const float* __restrict__ b, float* h) {
    float mu = 0.25f * (x.x + x.y + x.z + x.w);
    float d0 = x.x - mu, d1 = x.y - mu, d2 = x.z - mu, d3 = x.w - mu;
    float var = 0.25f * (d0 * d0 + d1 * d1 + d2 * d2 + d3 * d3);
    float r = rsqrtf(var + 1e-5f);
    h[0] = d0 * r * __ldg(g + 0) + __ldg(b + 0);
    h[1] = d1 * r * __ldg(g + 1) + __ldg(b + 1);
    h[2] = d2 * r * __ldg(g + 2) + __ldg(b + 2);
    h[3] = d3 * r * __ldg(g + 3) + __ldg(b + 3);
}

// qkv projection for one token, write q/k/v in (b,h,s,d) float2 layout
__device__ __forceinline__ void qkv_project(int t, const float* h,
                                            const float* __restrict__ wqkv_l) {
    float acc[12];
#pragma unroll
    for (int f = 0; f < 12; f++) {
        const float* w = wqkv_l + f * EE;
        acc[f] = h[0] * __ldg(w) + h[1] * __ldg(w + 1) +
                 h[2] * __ldg(w + 2) + h[3] * __ldg(w + 3);
    }
    int b = t >> 10;            // t / S
    int s = t & (SS - 1);
    // fold 1/sqrt(D) * log2(e) into q so attn does exp2 with no extra mul
    const float qs = 0.70710678118654752f * 1.4426950408889634f;
    g_q[(b * HH + 0) * SS + s] = make_float2(acc[0] * qs, acc[1] * qs);
    g_q[(b * HH + 1) * SS + s] = make_float2(acc[2] * qs, acc[3] * qs);
    g_k[(b * HH + 0) * SS + s] = make_float2(acc[4], acc[5]);
    g_k[(b * HH + 1) * SS + s] = make_float2(acc[6], acc[7]);
    g_v[(b * HH + 0) * SS + s] = make_float2(acc[8], acc[9]);
    g_v[(b * HH + 1) * SS + s] = make_float2(acc[10], acc[11]);
}

__device__ __forceinline__ float gelu_exact(float x) {
    return 0.5f * x * (1.0f + erff(x * 0.70710678118654752f));
}

// ---------------------------------------------------------------------------
// Kernel 1: embedding + LN1 + QKV (layer 0)
// ---------------------------------------------------------------------------
__global__ void embed_qkv_kernel(const int* __restrict__ token_ids,
                                 const float* __restrict__ emb,
                                 const float* __restrict__ ln1_g,
                                 const float* __restrict__ ln1_b,
                                 const float* __restrict__ wqkv) {
    int t = blockIdx.x * blockDim.x + threadIdx.x;
    if (t >= NT) return;
    int tok = __ldg(token_ids + t);
    const float* e = emb + tok * EE;
    float4 x = make_float4(__ldg(e), __ldg(e + 1), __ldg(e + 2), __ldg(e + 3));
    g_x[t] = x;
    float h[EE];
    layernorm4(x, ln1_g, ln1_b, h);
    qkv_project(t, h, wqkv);
}

// ---------------------------------------------------------------------------
// Kernel 2: attention. Single pass: M = |q|*max|k| upper bound (softmax is
// shift-invariant; bound keeps exp2 args in (-~30, 0], no overflow, dominant
// terms far above underflow).
// grid = BHN*4 = 256 blocks, 128 threads, 2 queries/thread (256 q / block).
// ---------------------------------------------------------------------------
__global__ void __launch_bounds__(128) attn_kernel() {
    __shared__ u64 sKx[SS];        // {kx,kx} replicated pairs
    __shared__ u64 sKy[SS];        // {ky,ky}
    __shared__ u64 sV[SS];         // {vx,vy}
    __shared__ unsigned sMaxBits;  // max |k|^2 over the (b,h), as ordered bits

    int bh    = blockIdx.x >> 2;
    int qbase = (blockIdx.x & 3) * 256;

    if (threadIdx.x == 0) sMaxBits = 0u;
    __syncthreads();

    const float2* __restrict__ Kg = g_k + bh * SS;
    const float2* __restrict__ Vg = g_v + bh * SS;
    float locmax = 0.f;
    for (int i = threadIdx.x; i < SS; i += 128) {
        float2 kk = Kg[i];
        float2 vv = Vg[i];
        sKx[i] = pack2(kk.x, kk.x);
        sKy[i] = pack2(kk.y, kk.y);
        sV[i]  = pack2(vv.x, vv.y);
        float n2 = fmaf(kk.x, kk.x, kk.y * kk.y);
        locmax = fmaxf(locmax, n2);
    }
    atomicMax(&sMaxBits, __float_as_uint(locmax));
    __syncthreads();
    float maxKn = sqrtf(__uint_as_float(sMaxBits));

    int qi0 = qbase + threadIdx.x;
    int qi1 = qi0 + 128;
    float2 qa = g_q[bh * SS + qi0];   // already scaled by log2e/sqrt(D)
    float2 qb = g_q[bh * SS + qi1];

    float mA = sqrtf(fmaf(qa.x, qa.x, qa.y * qa.y)) * maxKn;
    float mB = sqrtf(fmaf(qb.x, qb.x, qb.y * qb.y)) * maxKn;
    u64 m2  = pack2(-mA, -mB);
    u64 qx2 = pack2(qa.x, qb.x);
    u64 qy2 = pack2(qa.y, qb.y);

    float suma = 0.f, sumb = 0.f;
    u64 accA = pack2(0.f, 0.f);
    u64 accB = accA;

#pragma unroll 8
    for (int j = 0; j < SS; j++) {
        u64 kxx = sKx[j];
        u64 kyy = sKy[j];
        u64 vv2 = sV[j];
        u64 arg2;
        FMA2(arg2, qy2, kyy, m2);
        FMA2(arg2, qx2, kxx, arg2);
        float a0, a1;
        unpack2(arg2, a0, a1);
        float pa = ex2f(a0);
        float pb = ex2f(a1);
        suma += pa;
        sumb += pb;
        u64 paa = pack2(pa, pa);
        u64 pbb = pack2(pb, pb);
        FMA2(accA, paa, vv2, accA);
        FMA2(accB, pbb, vv2, accB);
    }

    float ax, ay, bx, by;
    unpack2(accA, ax, ay);
    unpack2(accB, bx, by);
    float ra = __frcp_rn(suma);
    float rb = __frcp_rn(sumb);
    g_o[bh * SS + qi0] = make_float2(ax * ra, ay * ra);
    g_o[bh * SS + qi1] = make_float2(bx * rb, by * rb);
}

// ---------------------------------------------------------------------------
// Kernel 3: x += wo*o ; FFN ; then either LN1+QKV of next layer or final logits
// ---------------------------------------------------------------------------
__global__ void post_attn_kernel(const float* __restrict__ wo_l,
                                 const float* __restrict__ ln2_g_l,
                                 const float* __restrict__ ln2_b_l,
                                 const float* __restrict__ w1_l,
                                 const float* __restrict__ b1_l,
                                 const float* __restrict__ w2_l,
                                 const float* __restrict__ b2_l,
                                 const float* __restrict__ ln1_g_next,  // null if last
                                 const float* __restrict__ ln1_b_next,
                                 const float* __restrict__ wqkv_next,
                                 const float* __restrict__ out_w,       // used if last
                                 float* __restrict__ out,
                                 int last) {
    int t = blockIdx.x * blockDim.x + threadIdx.x;
    if (t >= NT) return;
    int b = t >> 10;
    int s = t & (SS - 1);

    float4 x = g_x[t];
    float2 o0 = g_o[(b * HH + 0) * SS + s];
    float2 o1 = g_o[(b * HH + 1) * SS + s];
    float o[EE] = {o0.x, o0.y, o1.x, o1.y};

    // x += wo @ o
    float xv[EE] = {x.x, x.y, x.z, x.w};
#pragma unroll
    for (int f = 0; f < EE; f++) {
        const float* w = wo_l + f * EE;
        xv[f] += o[0] * __ldg(w) + o[1] * __ldg(w + 1) +
                 o[2] * __ldg(w + 2) + o[3] * __ldg(w + 3);
    }
    float4 xr = make_float4(xv[0], xv[1], xv[2], xv[3]);

    // FFN: x += w2 @ gelu(w1 @ LN2(x) + b1) + b2
    float h[EE];
    layernorm4(xr, ln2_g_l, ln2_b_l, h);
    float f1[FF];
#pragma unroll
    for (int f = 0; f < FF; f++) {
        const float* w = w1_l + f * EE;
        float acc = __ldg(b1_l + f) + h[0] * __ldg(w) + h[1] * __ldg(w + 1) +
                    h[2] * __ldg(w + 2) + h[3] * __ldg(w + 3);
        f1[f] = gelu_exact(acc);
    }
#pragma unroll
    for (int e = 0; e < EE; e++) {
        const float* w = w2_l + e * FF;
        float acc = __ldg(b2_l + e);
#pragma unroll
        for (int f = 0; f < FF; f++) acc = fmaf(f1[f], __ldg(w + f), acc);
        xv[e] += acc;
    }
    xr = make_float4(xv[0], xv[1], xv[2], xv[3]);
    g_x[t] = xr;

    if (last) {
        // logits = x @ out_w^T   [V=8]
#pragma unroll
        for (int v = 0; v < VV; v++) {
            const float* w = out_w + v * EE;
            out[t * VV + v] = xv[0] * __ldg(w) + xv[1] * __ldg(w + 1) +
                              xv[2] * __ldg(w + 2) + xv[3] * __ldg(w + 3);
        }
    } else {
        float hn[EE];
        layernorm4(xr, ln1_g_next, ln1_b_next, hn);
        qkv_project(t, hn, wqkv_next);
    }
}

// ---------------------------------------------------------------------------
// launch
// ---------------------------------------------------------------------------
extern "C" void kernel_launch(void* const* d_in, const int* in_sizes, int n_in,
                              void* d_out, int out_size) {
    const int*   token_ids = (const int*)d_in[0];
    const float* emb   = (const float*)d_in[1];
    const float* ln1_g = (const float*)d_in[2];
    const float* ln1_b = (const float*)d_in[3];
    const float* wqkv  = (const float*)d_in[4];
    const float* wo    = (const float*)d_in[5];
    const float* ln2_g = (const float*)d_in[6];
    const float* ln2_b = (const float*)d_in[7];
    const float* w1    = (const float*)d_in[8];
    const float* b1    = (const float*)d_in[9];
    const float* w2    = (const float*)d_in[10];
    const float* b2    = (const float*)d_in[11];
    const float* out_w = (const float*)d_in[12];
    float* out = (float*)d_out;

    const int TPB = 256;
    const int TOK_BLOCKS = NT / TPB;       // 128
    const int ATTN_BLOCKS = BHN * 4;       // 256
    const int ATTN_TPB = 128;

    // Layer 0
    embed_qkv_kernel<<<TOK_BLOCKS, TPB>>>(token_ids, emb, ln1_g, ln1_b, wqkv);
    attn_kernel<<<ATTN_BLOCKS, ATTN_TPB>>>();
    post_attn_kernel<<<TOK_BLOCKS, TPB>>>(
        wo + 0 * EE * EE, ln2_g + 0 * EE, ln2_b + 0 * EE,
        w1 + 0 * FF * EE, b1 + 0 * FF, w2 + 0 * EE * FF, b2 + 0 * EE,
        ln1_g + 1 * EE, ln1_b + 1 * EE, wqkv + 1 * 3 * EE * EE,
        out_w, out, /*last=*/0);

    // Layer 1
    attn_kernel<<<ATTN_BLOCKS, ATTN_TPB>>>();
    post_attn_kernel<<<TOK_BLOCKS, TPB>>>(
        wo + 1 * EE * EE, ln2_g + 1 * EE, ln2_b + 1 * EE,
        w1 + 1 * FF * EE, b1 + 1 * FF, w2 + 1 * EE * FF, b2 + 1 * EE,
        nullptr, nullptr, nullptr,
        out_w, out, /*last=*/1);
}

// round 3
// speedup vs baseline: 1.4750x; 1.0524x over previous
#include <cuda_runtime.h>
#include <math.h>

// Problem constants
#define BB   32
#define SS   1024
#define HH   2
#define EE   4
#define FF   16
#define VV   8
#define NT   (BB * SS)      // 32768 tokens
#define BHN  (BB * HH)      // 64 (b,h) pairs
#define NSPLIT 4
#define KCH  (SS / NSPLIT)  // 256 keys per block

typedef unsigned long long u64;

// Scratch (no runtime allocation allowed)
__device__ float4 g_x[NT];                 // residual stream [token][E]
__device__ float2 g_q[BHN * SS];           // per-(b,h) q, pre-scaled
__device__ float2 g_k[BHN * SS];
__device__ float2 g_v[BHN * SS];
__device__ float4 g_part[BHN * SS * NSPLIT]; // (m, sum, ax, ay) partials

// ---------------------------------------------------------------------------
// f32x2 packed-math helpers (sm_103a)
// ---------------------------------------------------------------------------
__device__ __forceinline__ u64 pack2(float lo, float hi) {
    u64 r;
    asm("mov.b64 %0, {%1, %2};" : "=l"(r)
        : "r"(__float_as_uint(lo)), "r"(__float_as_uint(hi)));
    return r;
}
__device__ __forceinline__ void unpack2(u64 v, float& lo, float& hi) {
    unsigned a, b;
    asm("mov.b64 {%0, %1}, %2;" : "=r"(a), "=r"(b) : "l"(v));
    lo = __uint_as_float(a);
    hi = __uint_as_float(b);
}
#define FMA2(d, a, b, c) \
    asm("fma.rn.f32x2 %0, %1, %2, %3;" : "=l"(d) : "l"(a), "l"(b), "l"(c))
#define ADD2(d, a, b) \
    asm("add.rn.f32x2 %0, %1, %2;" : "=l"(d) : "l"(a), "l"(b))

__device__ __forceinline__ float ex2f(float x) {
    float r;
    asm("ex2.approx.f32 %0, %1;" : "=f"(r) : "f"(x));
    return r;
}

// ---------------------------------------------------------------------------
// scalar helpers
// ---------------------------------------------------------------------------
__device__ __forceinline__ void layernorm4(float4 x, const float* __restrict__ g,
                                           const float* __restrict__ b, float* h) {
    float mu = 0.25f * (x.x + x.y + x.z + x.w);
    float d0 = x.x - mu, d1 = x.y - mu, d2 = x.z - mu, d3 = x.w - mu;
    float var = 0.25f * (d0 * d0 + d1 * d1 + d2 * d2 + d3 * d3);
    float r = rsqrtf(var + 1e-5f);
    h[0] = d0 * r * __ldg(g + 0) + __ldg(b + 0);
    h[1] = d1 * r * __ldg(g + 1) + __ldg(b + 1);
    h[2] = d2 * r * __ldg(g + 2) + __ldg(b + 2);
    h[3] = d3 * r * __ldg(g + 3) + __ldg(b + 3);
}

// qkv projection for one token, write q/k/v in (b,h,s,d) float2 layout
__device__ __forceinline__ void qkv_project(int t, const float* h,
                                            const float* __restrict__ wqkv_l) {
    float acc[12];
#pragma unroll
    for (int f = 0; f < 12; f++) {
        const float* w = wqkv_l + f * EE;
        acc[f] = h[0] * __ldg(w) + h[1] * __ldg(w + 1) +
                 h[2] * __ldg(w + 2) + h[3] * __ldg(w + 3);
    }
    int b = t >> 10;            // t / S
    int s = t & (SS - 1);
    // fold 1/sqrt(D) * log2(e) into q so attn does exp2 with no extra mul
    const float qs = 0.70710678118654752f * 1.4426950408889634f;
    g_q[(b * HH + 0) * SS + s] = make_float2(acc[0] * qs, acc[1] * qs);
    g_q[(b * HH + 1) * SS + s] = make_float2(acc[2] * qs, acc[3] * qs);
    g_k[(b * HH + 0) * SS + s] = make_float2(acc[4], acc[5]);
    g_k[(b * HH + 1) * SS + s] = make_float2(acc[6], acc[7]);
    g_v[(b * HH + 0) * SS + s] = make_float2(acc[8], acc[9]);
    g_v[(b * HH + 1) * SS + s] = make_float2(acc[10], acc[11]);
}

__device__ __forceinline__ float gelu_exact(float x) {
    return 0.5f * x * (1.0f + erff(x * 0.70710678118654752f));
}

// ---------------------------------------------------------------------------
// Kernel 1: embedding + LN1 + QKV (layer 0)
// ---------------------------------------------------------------------------
__global__ void embed_qkv_kernel(const int* __restrict__ token_ids,
                                 const float* __restrict__ emb,
                                 const float* __restrict__ ln1_g,
                                 const float* __restrict__ ln1_b,
                                 const float* __restrict__ wqkv) {
    int t = blockIdx.x * blockDim.x + threadIdx.x;
    if (t >= NT) return;
    int tok = __ldg(token_ids + t);
    const float* e = emb + tok * EE;
    float4 x = make_float4(__ldg(e), __ldg(e + 1), __ldg(e + 2), __ldg(e + 3));
    g_x[t] = x;
    float h[EE];
    layernorm4(x, ln1_g, ln1_b, h);
    qkv_project(t, h, wqkv);
}

// ---------------------------------------------------------------------------
// Kernel 2: attention partials, split-K over NSPLIT chunks.
// Each block: one (bh, qchunk of 256 q, kchunk of 256 keys).
// Shift by per-(thread,chunk) upper bound m = |q|*max|k| (softmax is
// shift-invariant; partials carry m for the rescale combine).
// grid = 64 * 4 * 4 = 1024 blocks, 128 threads, 2 queries/thread.
// ---------------------------------------------------------------------------
__global__ void __launch_bounds__(128) attn_kernel() {
    __shared__ u64 sKx[KCH];       // {kx,kx}
    __shared__ u64 sKy[KCH];       // {ky,ky}
    __shared__ u64 sVx[KCH];       // {vx,vx}
    __shared__ u64 sVy[KCH];       // {vy,vy}
    __shared__ unsigned sMaxBits;  // max |k|^2 over this chunk (ordered bits)

    int bx = blockIdx.x;
    int bh    = bx >> 4;
    int qc    = (bx >> 2) & 3;
    int kc    = bx & 3;
    int qbase = qc * 256;
    int kbase = kc * KCH;

    if (threadIdx.x == 0) sMaxBits = 0u;
    __syncthreads();

    const float2* __restrict__ Kg = g_k + bh * SS + kbase;
    const float2* __restrict__ Vg = g_v + bh * SS + kbase;
    float locmax = 0.f;
#pragma unroll
    for (int i = threadIdx.x; i < KCH; i += 128) {
        float2 kk = Kg[i];
        float2 vv = Vg[i];
        sKx[i] = pack2(kk.x, kk.x);
        sKy[i] = pack2(kk.y, kk.y);
        sVx[i] = pack2(vv.x, vv.x);
        sVy[i] = pack2(vv.y, vv.y);
        locmax = fmaxf(locmax, fmaf(kk.x, kk.x, kk.y * kk.y));
    }
    atomicMax(&sMaxBits, __float_as_uint(locmax));
    __syncthreads();
    float maxKn = sqrtf(__uint_as_float(sMaxBits));

    int qi0 = qbase + threadIdx.x;
    int qi1 = qi0 + 128;
    float2 qa = g_q[bh * SS + qi0];   // pre-scaled by log2e/sqrt(D)
    float2 qb = g_q[bh * SS + qi1];

    float mA = sqrtf(fmaf(qa.x, qa.x, qa.y * qa.y)) * maxKn;
    float mB = sqrtf(fmaf(qb.x, qb.x, qb.y * qb.y)) * maxKn;
    u64 m2  = pack2(-mA, -mB);
    u64 qx2 = pack2(qa.x, qb.x);
    u64 qy2 = pack2(qa.y, qb.y);

    u64 sum2 = pack2(0.f, 0.f);   // {sumA, sumB}
    u64 accX = sum2;              // {axA, axB}
    u64 accY = sum2;              // {ayA, ayB}

#pragma unroll 8
    for (int j = 0; j < KCH; j++) {
        u64 kxx = sKx[j];
        u64 kyy = sKy[j];
        u64 vxx = sVx[j];
        u64 vyy = sVy[j];
        u64 arg2;
        FMA2(arg2, qy2, kyy, m2);
        FMA2(arg2, qx2, kxx, arg2);
        float a0, a1;
        unpack2(arg2, a0, a1);
        float pa = ex2f(a0);
        float pb = ex2f(a1);
        u64 p2 = pack2(pa, pb);
        ADD2(sum2, sum2, p2);
        FMA2(accX, p2, vxx, accX);
        FMA2(accY, p2, vyy, accY);
    }

    float sA, sB, axA, axB, ayA, ayB;
    unpack2(sum2, sA, sB);
    unpack2(accX, axA, axB);
    unpack2(accY, ayA, ayB);
    float4* P = g_part + (bh * SS) * NSPLIT;
    P[qi0 * NSPLIT + kc] = make_float4(mA, sA, axA, ayA);
    P[qi1 * NSPLIT + kc] = make_float4(mB, sB, axB, ayB);
}

// ---------------------------------------------------------------------------
// Kernel 3: combine attn partials; x += wo*o ; FFN ;
// then either LN1+QKV of next layer or final logits
// ---------------------------------------------------------------------------
__global__ void post_attn_kernel(const float* __restrict__ wo_l,
                                 const float* __restrict__ ln2_g_l,
                                 const float* __restrict__ ln2_b_l,
                                 const float* __restrict__ w1_l,
                                 const float* __restrict__ b1_l,
                                 const float* __restrict__ w2_l,
                                 const float* __restrict__ b2_l,
                                 const float* __restrict__ ln1_g_next,  // null if last
                                 const float* __restrict__ ln1_b_next,
                                 const float* __restrict__ wqkv_next,
                                 const float* __restrict__ out_w,       // used if last
                                 float* __restrict__ out,
                                 int last) {
    int t = blockIdx.x * blockDim.x + threadIdx.x;
    if (t >= NT) return;
    int b = t >> 10;
    int s = t & (SS - 1);

    // combine split-K softmax partials for both heads
    float o[EE];
#pragma unroll
    for (int h = 0; h < HH; h++) {
        const float4* P = g_part + ((b * HH + h) * SS + s) * NSPLIT;
        float4 p0 = P[0], p1 = P[1], p2 = P[2], p3 = P[3];
        float mm = fmaxf(fmaxf(p0.x, p1.x), fmaxf(p2.x, p3.x));
        float s0 = ex2f(p0.x - mm), s1 = ex2f(p1.x - mm);
        float s2 = ex2f(p2.x - mm), s3 = ex2f(p3.x - mm);
        float S  = p0.y * s0 + p1.y * s1 + p2.y * s2 + p3.y * s3;
        float ox = p0.z * s0 + p1.z * s1 + p2.z * s2 + p3.z * s3;
        float oy = p0.w * s0 + p1.w * s1 + p2.w * s2 + p3.w * s3;
        float r = __frcp_rn(S);
        o[h * 2 + 0] = ox * r;
        o[h * 2 + 1] = oy * r;
    }

    float4 x = g_x[t];
    float xv[EE] = {x.x, x.y, x.z, x.w};
    // x += wo @ o
#pragma unroll
    for (int f = 0; f < EE; f++) {
        const float* w = wo_l + f * EE;
        xv[f] += o[0] * __ldg(w) + o[1] * __ldg(w + 1) +
                 o[2] * __ldg(w + 2) + o[3] * __ldg(w + 3);
    }
    float4 xr = make_float4(xv[0], xv[1], xv[2], xv[3]);

    // FFN: x += w2 @ gelu(w1 @ LN2(x) + b1) + b2
    float h2[EE];
    layernorm4(xr, ln2_g_l, ln2_b_l, h2);
    float f1[FF];
#pragma unroll
    for (int f = 0; f < FF; f++) {
        const float* w = w1_l + f * EE;
        float acc = __ldg(b1_l + f) + h2[0] * __ldg(w) + h2[1] * __ldg(w + 1) +
                    h2[2] * __ldg(w + 2) + h2[3] * __ldg(w + 3);
        f1[f] = gelu_exact(acc);
    }
#pragma unroll
    for (int e = 0; e < EE; e++) {
        const float* w = w2_l + e * FF;
        float acc = __ldg(b2_l + e);
#pragma unroll
        for (int f = 0; f < FF; f++) acc = fmaf(f1[f], __ldg(w + f), acc);
        xv[e] += acc;
    }
    xr = make_float4(xv[0], xv[1], xv[2], xv[3]);
    g_x[t] = xr;

    if (last) {
#pragma unroll
        for (int v = 0; v < VV; v++) {
            const float* w = out_w + v * EE;
            out[t * VV + v] = xv[0] * __ldg(w) + xv[1] * __ldg(w + 1) +
                              xv[2] * __ldg(w + 2) + xv[3] * __ldg(w + 3);
        }
    } else {
        float hn[EE];
        layernorm4(xr, ln1_g_next, ln1_b_next, hn);
        qkv_project(t, hn, wqkv_next);
    }
}

// ---------------------------------------------------------------------------
// launch
// ---------------------------------------------------------------------------
extern "C" void kernel_launch(void* const* d_in, const int* in_sizes, int n_in,
                              void* d_out, int out_size) {
    const int*   token_ids = (const int*)d_in[0];
    const float* emb   = (const float*)d_in[1];
    const float* ln1_g = (const float*)d_in[2];
    const float* ln1_b = (const float*)d_in[3];
    const float* wqkv  = (const float*)d_in[4];
    const float* wo    = (const float*)d_in[5];
    const float* ln2_g = (const float*)d_in[6];
    const float* ln2_b = (const float*)d_in[7];
    const float* w1    = (const float*)d_in[8];
    const float* b1    = (const float*)d_in[9];
    const float* w2    = (const float*)d_in[10];
    const float* b2    = (const float*)d_in[11];
    const float* out_w = (const float*)d_in[12];
    float* out = (float*)d_out;

    const int TPB = 256;
    const int TOK_BLOCKS = NT / TPB;                 // 128
    const int ATTN_BLOCKS = BHN * 4 * NSPLIT;        // 1024
    const int ATTN_TPB = 128;

    // Layer 0
    embed_qkv_kernel<<<TOK_BLOCKS, TPB>>>(token_ids, emb, ln1_g, ln1_b, wqkv);
    attn_kernel<<<ATTN_BLOCKS, ATTN_TPB>>>();
    post_attn_kernel<<<TOK_BLOCKS, TPB>>>(
        wo + 0 * EE * EE, ln2_g + 0 * EE, ln2_b + 0 * EE,
        w1 + 0 * FF * EE, b1 + 0 * FF, w2 + 0 * EE * FF, b2 + 0 * EE,
        ln1_g + 1 * EE, ln1_b + 1 * EE, wqkv + 1 * 3 * EE * EE,
        out_w, out, /*last=*/0);

    // Layer 1
    attn_kernel<<<ATTN_BLOCKS, ATTN_TPB>>>();
    post_attn_kernel<<<TOK_BLOCKS, TPB>>>(
        wo + 1 * EE * EE, ln2_g + 1 * EE, ln2_b + 1 * EE,
        w1 + 1 * FF * EE, b1 + 1 * FF, w2 + 1 * EE * FF, b2 + 1 * EE,
        nullptr, nullptr, nullptr,
        out_w, out, /*last=*/1);
}